// round 2
// baseline (speedup 1.0000x reference)
#include <cuda_runtime.h>

#define BB 512
#define NN 2048
#define QDIM 64
#define HH 8
#define KDIM 8
#define VDIM 8
#define ODIM 64

// device scratch (no allocations allowed)
__device__ float g_qavg[BB * QDIM];          // [B][64]
__device__ float g_wavg[BB * HH * VDIM];     // [B][64]  (h*8+v)

// ---------------------------------------------------------------------------
// Kernel 1: masked mean of q_data over N  -> g_qavg
// one block per batch, 256 threads: c = t&63 (channel), g = t>>6 (row group)
// ---------------------------------------------------------------------------
__global__ void __launch_bounds__(256) k1_qavg(const float* __restrict__ q_data,
                                               const float* __restrict__ q_mask) {
    int b = blockIdx.x;
    int t = threadIdx.x;
    int c = t & 63;
    int g = t >> 6;
    const float* qb = q_data + (size_t)b * NN * QDIM;
    const float* mb = q_mask + (size_t)b * NN;
    float acc = 0.f, ms = 0.f;
    for (int n = g; n < NN; n += 4) {
        float qm = mb[n];
        acc += qm * qb[(size_t)n * QDIM + c];
        ms += qm;
    }
    __shared__ float sm[4][64];
    __shared__ float smm[4][64];
    sm[g][c] = acc;
    smm[g][c] = ms;
    __syncthreads();
    if (t < 64) {
        float tot = sm[0][t] + sm[1][t] + sm[2][t] + sm[3][t];
        float mt = smm[0][0] + smm[1][0] + smm[2][0] + smm[3][0];
        g_qavg[b * QDIM + t] = tot / (mt + 1e-10f);
    }
}

// ---------------------------------------------------------------------------
// Kernel 2: per-batch attention -> g_wavg[b][h*8+v]
// q = (q_avg @ query_w) * kd^-0.5 ;  logits[h,n] = m[n,:] . (key_w @ q[h]) + bias
// online softmax + weighted sum of v = m @ value_w, all in one pass over N.
// one block per batch, 256 threads, each thread owns 8 rows (n = t + 256*it).
// ---------------------------------------------------------------------------
__global__ void __launch_bounds__(256) k2_attn(
    const float* __restrict__ m_data, const float* __restrict__ q_mask,
    const float* __restrict__ query_w, const float* __restrict__ key_w,
    const float* __restrict__ value_w)
{
    int b = blockIdx.x;
    int t = threadIdx.x;

    __shared__ __align__(16) float kw_s[QDIM][KDIM];   // [64][8]
    __shared__ __align__(16) float vw_s[QDIM][VDIM];   // [64][8]
    __shared__ __align__(16) float p_s[QDIM][HH];      // [64][8] : key_w @ q
    __shared__ float qs_s[HH * KDIM];                  // 64
    __shared__ float qavg_s[QDIM];

    if (t < QDIM) qavg_s[t] = g_qavg[b * QDIM + t];
    for (int i = t; i < QDIM * KDIM; i += 256) {
        kw_s[i >> 3][i & 7] = key_w[i];
        vw_s[i >> 3][i & 7] = value_w[i];
    }
    __syncthreads();
    if (t < 64) {
        float v = 0.f;
        for (int a = 0; a < QDIM; ++a) v += qavg_s[a] * query_w[a * 64 + t];
        qs_s[t] = v * 0.3535533905932738f;   // KD^-0.5
    }
    __syncthreads();
    // p_s[a][h] = sum_kd key_w[a][kd] * q[h][kd]
    for (int i = t; i < QDIM * HH; i += 256) {
        int a = i >> 3, h = i & 7;
        float v = 0.f;
        #pragma unroll
        for (int kd = 0; kd < 8; ++kd) v += kw_s[a][kd] * qs_s[h * 8 + kd];
        p_s[a][h] = v;
    }
    __syncthreads();

    float mx[HH], sum[HH], acc[HH][VDIM];
    #pragma unroll
    for (int h = 0; h < HH; ++h) {
        mx[h] = -1e30f; sum[h] = 0.f;
        #pragma unroll
        for (int c = 0; c < VDIM; ++c) acc[h][c] = 0.f;
    }

    const float4* mp4 = (const float4*)(m_data + (size_t)b * NN * QDIM);
    const float* qmp = q_mask + (size_t)b * NN;

    for (int it = 0; it < NN / 256; ++it) {
        int n = t + it * 256;
        float bias = 32768.f * (qmp[n] - 1.f);
        float lg[HH];
        float v[VDIM];
        #pragma unroll
        for (int h = 0; h < HH; ++h) lg[h] = bias;
        #pragma unroll
        for (int c = 0; c < VDIM; ++c) v[c] = 0.f;
        const float4* mp = mp4 + (size_t)n * (QDIM / 4);
        #pragma unroll 4
        for (int a4 = 0; a4 < 16; ++a4) {
            float4 mv = mp[a4];
            float mvals[4] = {mv.x, mv.y, mv.z, mv.w};
            #pragma unroll
            for (int j = 0; j < 4; ++j) {
                int a = a4 * 4 + j;
                float mm = mvals[j];
                const float4* pp = (const float4*)&p_s[a][0];
                const float4* vp = (const float4*)&vw_s[a][0];
                float4 p0 = pp[0], p1 = pp[1];
                float4 v0 = vp[0], v1 = vp[1];
                lg[0] += mm * p0.x; lg[1] += mm * p0.y; lg[2] += mm * p0.z; lg[3] += mm * p0.w;
                lg[4] += mm * p1.x; lg[5] += mm * p1.y; lg[6] += mm * p1.z; lg[7] += mm * p1.w;
                v[0] += mm * v0.x; v[1] += mm * v0.y; v[2] += mm * v0.z; v[3] += mm * v0.w;
                v[4] += mm * v1.x; v[5] += mm * v1.y; v[6] += mm * v1.z; v[7] += mm * v1.w;
            }
        }
        // online softmax update (one new element per head)
        #pragma unroll
        for (int h = 0; h < HH; ++h) {
            float M = fmaxf(mx[h], lg[h]);
            float sc = __expf(mx[h] - M);
            float p = __expf(lg[h] - M);
            sum[h] = sum[h] * sc + p;
            #pragma unroll
            for (int c = 0; c < VDIM; ++c) acc[h][c] = acc[h][c] * sc + p * v[c];
            mx[h] = M;
        }
    }

    // intra-warp butterfly merge of (m, s, acc[8]) per head
    #pragma unroll
    for (int off = 16; off; off >>= 1) {
        #pragma unroll
        for (int h = 0; h < HH; ++h) {
            float m2 = __shfl_xor_sync(0xffffffffu, mx[h], off);
            float s2 = __shfl_xor_sync(0xffffffffu, sum[h], off);
            float M = fmaxf(mx[h], m2);
            float e1 = __expf(mx[h] - M);
            float e2 = __expf(m2 - M);
            sum[h] = sum[h] * e1 + s2 * e2;
            #pragma unroll
            for (int c = 0; c < VDIM; ++c) {
                float a2 = __shfl_xor_sync(0xffffffffu, acc[h][c], off);
                acc[h][c] = acc[h][c] * e1 + a2 * e2;
            }
            mx[h] = M;
        }
    }

    __shared__ float red[8][HH][10];
    int w = t >> 5, lane = t & 31;
    if (lane == 0) {
        #pragma unroll
        for (int h = 0; h < HH; ++h) {
            red[w][h][0] = mx[h];
            red[w][h][1] = sum[h];
            #pragma unroll
            for (int c = 0; c < 8; ++c) red[w][h][2 + c] = acc[h][c];
        }
    }
    __syncthreads();
    if (t < HH) {
        int h = t;
        float M = -1e30f, S = 0.f, A[8];
        #pragma unroll
        for (int c = 0; c < 8; ++c) A[c] = 0.f;
        for (int w2 = 0; w2 < 8; ++w2) {
            float m2 = red[w2][h][0], s2 = red[w2][h][1];
            float Mn = fmaxf(M, m2);
            float e1 = __expf(M - Mn), e2 = __expf(m2 - Mn);
            S = S * e1 + s2 * e2;
            #pragma unroll
            for (int c = 0; c < 8; ++c) A[c] = A[c] * e1 + red[w2][h][2 + c] * e2;
            M = Mn;
        }
        float inv = 1.f / S;
        #pragma unroll
        for (int c = 0; c < 8; ++c) g_wavg[b * 64 + h * 8 + c] = A[c] * inv;
    }
}

// ---------------------------------------------------------------------------
// Kernel 3 (the hot one): per 128-token tile:
//   G = sigmoid(A @ W1 + b1) * wavg[b]   (A = q_data tile, [128,64]@[64,64])
//   out = G @ W2 + b2                    ([128,64]@[64,64])
// 256 threads, each computes an 8x4 register tile per GEMM.
// A is stored k-major in padded smem; the same buffer is reused for G.
// ---------------------------------------------------------------------------
#define TILE_T 128
#define APITCH 132

__global__ void __launch_bounds__(256) k3_gate(
    const float* __restrict__ q_data,
    const float* __restrict__ gating_w, const float* __restrict__ gating_b,
    const float* __restrict__ output_w, const float* __restrict__ output_b,
    float* __restrict__ out)
{
    extern __shared__ float smem[];
    float* W1 = smem;                    // [64][64]
    float* W2 = smem + 4096;             // [64][64]
    float* A  = smem + 8192;             // [64][APITCH] k-major
    __shared__ float b1s[64], b2s[64], was[64];

    int t = threadIdx.x;
    size_t tok0 = (size_t)blockIdx.x * TILE_T;
    int b = (int)(tok0 >> 11);           // / 2048

    for (int i = t; i < 4096; i += 256) {
        W1[i] = gating_w[i];
        W2[i] = output_w[i];
    }
    if (t < 64) {
        b1s[t] = gating_b[t];
        b2s[t] = output_b[t];
        was[t] = g_wavg[b * 64 + t];
    }
    // load q_data tile coalesced, store transposed (k-major) into A
    const float4* qp = (const float4*)(q_data + tok0 * QDIM);
    #pragma unroll
    for (int i = t; i < TILE_T * 16; i += 256) {
        float4 vv = qp[i];
        int row = i >> 4;
        int k = (i & 15) << 2;
        A[(k + 0) * APITCH + row] = vv.x;
        A[(k + 1) * APITCH + row] = vv.y;
        A[(k + 2) * APITCH + row] = vv.z;
        A[(k + 3) * APITCH + row] = vv.w;
    }
    __syncthreads();

    int tx = t & 15, ty = t >> 4;
    int col0 = tx * 4, row0 = ty * 8;

    // ---- GEMM1: c1 = A @ W1 ----
    float c1[8][4];
    #pragma unroll
    for (int r = 0; r < 8; ++r)
        #pragma unroll
        for (int c = 0; c < 4; ++c) c1[r][c] = 0.f;

    #pragma unroll 8
    for (int k = 0; k < 64; ++k) {
        float4 w  = *(const float4*)&W1[k * 64 + col0];
        float4 a0 = *(const float4*)&A[k * APITCH + row0];
        float4 a1 = *(const float4*)&A[k * APITCH + row0 + 4];
        float av[8] = {a0.x, a0.y, a0.z, a0.w, a1.x, a1.y, a1.z, a1.w};
        float wv[4] = {w.x, w.y, w.z, w.w};
        #pragma unroll
        for (int r = 0; r < 8; ++r)
            #pragma unroll
            for (int c = 0; c < 4; ++c) c1[r][c] += av[r] * wv[c];
    }

    // ---- gate: sigmoid(+bias) * wavg, write back k-major into A ----
    float bl[4], wl[4];
    #pragma unroll
    for (int c = 0; c < 4; ++c) { bl[c] = b1s[col0 + c]; wl[c] = was[col0 + c]; }
    __syncthreads();   // everyone done reading A
    #pragma unroll
    for (int r = 0; r < 8; ++r) {
        #pragma unroll
        for (int c = 0; c < 4; ++c) {
            float x = c1[r][c] + bl[c];
            float gt = wl[c] / (1.f + __expf(-x));
            A[(col0 + c) * APITCH + row0 + r] = gt;
        }
    }
    __syncthreads();

    // ---- GEMM2: out = G @ W2 + b2 ----
    float c2[8][4];
    #pragma unroll
    for (int r = 0; r < 8; ++r)
        #pragma unroll
        for (int c = 0; c < 4; ++c) c2[r][c] = 0.f;

    #pragma unroll 8
    for (int k = 0; k < 64; ++k) {
        float4 w  = *(const float4*)&W2[k * 64 + col0];
        float4 a0 = *(const float4*)&A[k * APITCH + row0];
        float4 a1 = *(const float4*)&A[k * APITCH + row0 + 4];
        float av[8] = {a0.x, a0.y, a0.z, a0.w, a1.x, a1.y, a1.z, a1.w};
        float wv[4] = {w.x, w.y, w.z, w.w};
        #pragma unroll
        for (int r = 0; r < 8; ++r)
            #pragma unroll
            for (int c = 0; c < 4; ++c) c2[r][c] += av[r] * wv[c];
    }

    float* op = out + tok0 * ODIM;
    #pragma unroll
    for (int r = 0; r < 8; ++r) {
        float4 o;
        o.x = c2[r][0] + b2s[col0 + 0];
        o.y = c2[r][1] + b2s[col0 + 1];
        o.z = c2[r][2] + b2s[col0 + 2];
        o.w = c2[r][3] + b2s[col0 + 3];
        *(float4*)&op[(size_t)(row0 + r) * ODIM + col0] = o;
    }
}

// ---------------------------------------------------------------------------
extern "C" void kernel_launch(void* const* d_in, const int* in_sizes, int n_in,
                              void* d_out, int out_size) {
    (void)in_sizes; (void)n_in; (void)out_size;
    const float* q_data   = (const float*)d_in[0];
    const float* m_data   = (const float*)d_in[1];
    const float* q_mask   = (const float*)d_in[2];
    // d_in[3] = bias (dummy, unused by the reference math)
    const float* query_w  = (const float*)d_in[4];
    const float* key_w    = (const float*)d_in[5];
    const float* value_w  = (const float*)d_in[6];
    const float* gating_w = (const float*)d_in[7];
    const float* gating_b = (const float*)d_in[8];
    const float* output_w = (const float*)d_in[9];
    const float* output_b = (const float*)d_in[10];
    float* out = (float*)d_out;

    const int k3_smem = (8192 + 64 * APITCH) * 4;   // 66560 B
    cudaFuncSetAttribute(k3_gate, cudaFuncAttributeMaxDynamicSharedMemorySize, k3_smem);

    k1_qavg<<<BB, 256>>>(q_data, q_mask);
    k2_attn<<<BB, 256>>>(m_data, q_mask, query_w, key_w, value_w);
    k3_gate<<<(BB * NN) / TILE_T, 256, k3_smem>>>(q_data, gating_w, gating_b,
                                                  output_w, output_b, out);
}

// round 3
// speedup vs baseline: 1.3131x; 1.3131x over previous
#include <cuda_runtime.h>
#include <cstdint>

#define BB 512
#define NN 2048
#define QDIM 64
#define HH 8
#define KDIM 8
#define VDIM 8
#define ODIM 64

// device scratch (no allocations allowed)
__device__ float g_qavg[BB * QDIM];          // [B][64]
__device__ float g_wavg[BB * HH * VDIM];     // [B][64]  (h*8+v)

// ---------------------------------------------------------------------------
// helpers
// ---------------------------------------------------------------------------
__device__ __forceinline__ uint32_t f2tf32(float f) {
    uint32_t u;
    asm("cvt.rna.tf32.f32 %0, %1;" : "=r"(u) : "f"(f));
    return u;
}

__device__ __forceinline__ void mma_tf32(float c[4], const uint32_t a[4],
                                         const uint32_t b[2]) {
    asm volatile(
        "mma.sync.aligned.m16n8k8.row.col.f32.tf32.tf32.f32 "
        "{%0,%1,%2,%3}, {%4,%5,%6,%7}, {%8,%9}, {%0,%1,%2,%3};"
        : "+f"(c[0]), "+f"(c[1]), "+f"(c[2]), "+f"(c[3])
        : "r"(a[0]), "r"(a[1]), "r"(a[2]), "r"(a[3]), "r"(b[0]), "r"(b[1]));
}

// ---------------------------------------------------------------------------
// Kernel 1: masked mean of q_data over N  -> g_qavg
// 512 threads: c = t&63 (channel), g = t>>6 (row group, 8 groups)
// ---------------------------------------------------------------------------
__global__ void __launch_bounds__(512) k1_qavg(const float* __restrict__ q_data,
                                               const float* __restrict__ q_mask) {
    int b = blockIdx.x;
    int t = threadIdx.x;
    int c = t & 63;
    int g = t >> 6;
    const float* qb = q_data + (size_t)b * NN * QDIM;
    const float* mb = q_mask + (size_t)b * NN;
    float acc = 0.f, ms = 0.f;
    for (int n = g; n < NN; n += 8) {
        float qm = mb[n];
        acc += qm * qb[(size_t)n * QDIM + c];
        ms += qm;
    }
    __shared__ float sm[8][64];
    __shared__ float smm[8][64];
    sm[g][c] = acc;
    smm[g][c] = ms;
    __syncthreads();
    if (t < 64) {
        float tot = 0.f, mt = 0.f;
        #pragma unroll
        for (int gg = 0; gg < 8; ++gg) { tot += sm[gg][t]; mt += smm[gg][0]; }
        g_qavg[b * QDIM + t] = tot / (mt + 1e-10f);
    }
}

// ---------------------------------------------------------------------------
// Kernel 2: per-batch attention -> g_wavg[b][h*8+v]
// online softmax + weighted sum of v = m @ value_w, one pass over N.
// ---------------------------------------------------------------------------
__global__ void __launch_bounds__(256) k2_attn(
    const float* __restrict__ m_data, const float* __restrict__ q_mask,
    const float* __restrict__ query_w, const float* __restrict__ key_w,
    const float* __restrict__ value_w)
{
    int b = blockIdx.x;
    int t = threadIdx.x;

    __shared__ __align__(16) float kw_s[QDIM][KDIM];   // [64][8]
    __shared__ __align__(16) float vw_s[QDIM][VDIM];   // [64][8]
    __shared__ __align__(16) float p_s[QDIM][HH];      // [64][8] : key_w @ q
    __shared__ float qs_s[HH * KDIM];                  // 64
    __shared__ float qavg_s[QDIM];

    if (t < QDIM) qavg_s[t] = g_qavg[b * QDIM + t];
    for (int i = t; i < QDIM * KDIM; i += 256) {
        kw_s[i >> 3][i & 7] = key_w[i];
        vw_s[i >> 3][i & 7] = value_w[i];
    }
    __syncthreads();
    if (t < 64) {
        float v = 0.f;
        for (int a = 0; a < QDIM; ++a) v += qavg_s[a] * query_w[a * 64 + t];
        qs_s[t] = v * 0.3535533905932738f;   // KD^-0.5
    }
    __syncthreads();
    for (int i = t; i < QDIM * HH; i += 256) {
        int a = i >> 3, h = i & 7;
        float v = 0.f;
        #pragma unroll
        for (int kd = 0; kd < 8; ++kd) v += kw_s[a][kd] * qs_s[h * 8 + kd];
        p_s[a][h] = v;
    }
    __syncthreads();

    float mx[HH], sum[HH], acc[HH][VDIM];
    #pragma unroll
    for (int h = 0; h < HH; ++h) {
        mx[h] = -1e30f; sum[h] = 0.f;
        #pragma unroll
        for (int c = 0; c < VDIM; ++c) acc[h][c] = 0.f;
    }

    const float4* mp4 = (const float4*)(m_data + (size_t)b * NN * QDIM);
    const float* qmp = q_mask + (size_t)b * NN;

    for (int it = 0; it < NN / 256; ++it) {
        int n = t + it * 256;
        float bias = 32768.f * (qmp[n] - 1.f);
        float lg[HH];
        float v[VDIM];
        #pragma unroll
        for (int h = 0; h < HH; ++h) lg[h] = bias;
        #pragma unroll
        for (int c = 0; c < VDIM; ++c) v[c] = 0.f;
        const float4* mp = mp4 + (size_t)n * (QDIM / 4);
        #pragma unroll 4
        for (int a4 = 0; a4 < 16; ++a4) {
            float4 mv = mp[a4];
            float mvals[4] = {mv.x, mv.y, mv.z, mv.w};
            #pragma unroll
            for (int j = 0; j < 4; ++j) {
                int a = a4 * 4 + j;
                float mm = mvals[j];
                const float4* pp = (const float4*)&p_s[a][0];
                const float4* vp = (const float4*)&vw_s[a][0];
                float4 p0 = pp[0], p1 = pp[1];
                float4 v0 = vp[0], v1 = vp[1];
                lg[0] += mm * p0.x; lg[1] += mm * p0.y; lg[2] += mm * p0.z; lg[3] += mm * p0.w;
                lg[4] += mm * p1.x; lg[5] += mm * p1.y; lg[6] += mm * p1.z; lg[7] += mm * p1.w;
                v[0] += mm * v0.x; v[1] += mm * v0.y; v[2] += mm * v0.z; v[3] += mm * v0.w;
                v[4] += mm * v1.x; v[5] += mm * v1.y; v[6] += mm * v1.z; v[7] += mm * v1.w;
            }
        }
        #pragma unroll
        for (int h = 0; h < HH; ++h) {
            float M = fmaxf(mx[h], lg[h]);
            float sc = __expf(mx[h] - M);
            float p = __expf(lg[h] - M);
            sum[h] = sum[h] * sc + p;
            #pragma unroll
            for (int c = 0; c < VDIM; ++c) acc[h][c] = acc[h][c] * sc + p * v[c];
            mx[h] = M;
        }
    }

    #pragma unroll
    for (int off = 16; off; off >>= 1) {
        #pragma unroll
        for (int h = 0; h < HH; ++h) {
            float m2 = __shfl_xor_sync(0xffffffffu, mx[h], off);
            float s2 = __shfl_xor_sync(0xffffffffu, sum[h], off);
            float M = fmaxf(mx[h], m2);
            float e1 = __expf(mx[h] - M);
            float e2 = __expf(m2 - M);
            sum[h] = sum[h] * e1 + s2 * e2;
            #pragma unroll
            for (int c = 0; c < VDIM; ++c) {
                float a2 = __shfl_xor_sync(0xffffffffu, acc[h][c], off);
                acc[h][c] = acc[h][c] * e1 + a2 * e2;
            }
            mx[h] = M;
        }
    }

    __shared__ float red[8][HH][10];
    int w = t >> 5, lane = t & 31;
    if (lane == 0) {
        #pragma unroll
        for (int h = 0; h < HH; ++h) {
            red[w][h][0] = mx[h];
            red[w][h][1] = sum[h];
            #pragma unroll
            for (int c = 0; c < 8; ++c) red[w][h][2 + c] = acc[h][c];
        }
    }
    __syncthreads();
    if (t < HH) {
        int h = t;
        float M = -1e30f, S = 0.f, A[8];
        #pragma unroll
        for (int c = 0; c < 8; ++c) A[c] = 0.f;
        for (int w2 = 0; w2 < 8; ++w2) {
            float m2 = red[w2][h][0], s2 = red[w2][h][1];
            float Mn = fmaxf(M, m2);
            float e1 = __expf(M - Mn), e2 = __expf(m2 - Mn);
            S = S * e1 + s2 * e2;
            #pragma unroll
            for (int c = 0; c < 8; ++c) A[c] = A[c] * e1 + red[w2][h][2 + c] * e2;
            M = Mn;
        }
        float inv = 1.f / S;
        #pragma unroll
        for (int c = 0; c < 8; ++c) g_wavg[b * 64 + h * 8 + c] = A[c] * inv;
    }
}

// ---------------------------------------------------------------------------
// Kernel 3: tensor-core (tf32 mma.sync) gate path.
// Per block: 128-token tile.
//   G = sigmoid(A @ W1 + b1) * wavg[b];  out = G @ W2 + b2
// 8 warps, each owns 16 rows x 64 cols via m16n8k8 tf32 mma.
// Smem pitches chosen for conflict-free fragment loads:
//   A pitch 68  (4 mod 32): banks 4*gid + tid4 -> 32 distinct
//   W pitch 72  (8 mod 32): banks 8*r + c      -> 32 distinct
// ---------------------------------------------------------------------------
#define TILE_T 128
#define AP 68
#define WP 72
#define SM_W1 0
#define SM_W2 (64 * WP)
#define SM_A  (2 * 64 * WP)
#define K3_SMEM_FLOATS (2 * 64 * WP + TILE_T * AP)

__global__ void __launch_bounds__(256) k3_gate(
    const float* __restrict__ q_data,
    const float* __restrict__ gating_w, const float* __restrict__ gating_b,
    const float* __restrict__ output_w, const float* __restrict__ output_b,
    float* __restrict__ out)
{
    extern __shared__ float smem[];
    float* W1 = smem + SM_W1;            // [64][WP]  (k-major, same as gmem)
    float* W2 = smem + SM_W2;            // [64][WP]
    float* A  = smem + SM_A;             // [128][AP] row-major (tokens x k)
    __shared__ float b1s[64], b2s[64], was[64];

    int t = threadIdx.x;
    size_t tok0 = (size_t)blockIdx.x * TILE_T;
    int b = (int)(tok0 >> 11);           // / 2048

    // weights (already [k][n] in gmem) -> smem, converted to tf32
    for (int i = t; i < 4096; i += 256) {
        int k = i >> 6, n = i & 63;
        W1[k * WP + n] = __uint_as_float(f2tf32(gating_w[i]));
        W2[k * WP + n] = __uint_as_float(f2tf32(output_w[i]));
    }
    if (t < 64) {
        b1s[t] = gating_b[t];
        b2s[t] = output_b[t];
        was[t] = g_wavg[b * 64 + t];
    }
    // q_data tile -> smem row-major (converted to tf32)
    const float4* qp = (const float4*)(q_data + tok0 * QDIM);
    for (int i = t; i < TILE_T * 16; i += 256) {
        float4 v = qp[i];
        int row = i >> 4;
        int k = (i & 15) << 2;
        float* dst = &A[row * AP + k];
        dst[0] = __uint_as_float(f2tf32(v.x));
        dst[1] = __uint_as_float(f2tf32(v.y));
        dst[2] = __uint_as_float(f2tf32(v.z));
        dst[3] = __uint_as_float(f2tf32(v.w));
    }
    __syncthreads();

    int w = t >> 5, lane = t & 31;
    int gid = lane >> 2, tid4 = lane & 3;
    int row0 = w * 16;

    // ---------------- GEMM1: C = A @ W1 ----------------
    float c1[8][4];
    #pragma unroll
    for (int nt = 0; nt < 8; ++nt)
        #pragma unroll
        for (int j = 0; j < 4; ++j) c1[nt][j] = 0.f;

    #pragma unroll
    for (int k0 = 0; k0 < 8; ++k0) {
        int kk = k0 * 8;
        uint32_t a[4];
        const float* Ar = &A[(row0 + gid) * AP + kk + tid4];
        a[0] = __float_as_uint(Ar[0]);
        a[1] = __float_as_uint(Ar[8 * AP]);
        a[2] = __float_as_uint(Ar[4]);
        a[3] = __float_as_uint(Ar[8 * AP + 4]);
        #pragma unroll
        for (int nt = 0; nt < 8; ++nt) {
            uint32_t bf[2];
            const float* Bp = &W1[(kk + tid4) * WP + nt * 8 + gid];
            bf[0] = __float_as_uint(Bp[0]);
            bf[1] = __float_as_uint(Bp[4 * WP]);
            mma_tf32(c1[nt], a, bf);
        }
    }

    // ---------------- gate + write back into A (tf32) ----------------
    __syncthreads();   // all warps done reading A
    #pragma unroll
    for (int nt = 0; nt < 8; ++nt) {
        int col = nt * 8 + 2 * tid4;
        float bl0 = b1s[col], bl1 = b1s[col + 1];
        float wl0 = was[col], wl1 = was[col + 1];
        int r0 = row0 + gid, r1 = row0 + gid + 8;
        float g00 = wl0 / (1.f + __expf(-(c1[nt][0] + bl0)));
        float g01 = wl1 / (1.f + __expf(-(c1[nt][1] + bl1)));
        float g10 = wl0 / (1.f + __expf(-(c1[nt][2] + bl0)));
        float g11 = wl1 / (1.f + __expf(-(c1[nt][3] + bl1)));
        A[r0 * AP + col]     = __uint_as_float(f2tf32(g00));
        A[r0 * AP + col + 1] = __uint_as_float(f2tf32(g01));
        A[r1 * AP + col]     = __uint_as_float(f2tf32(g10));
        A[r1 * AP + col + 1] = __uint_as_float(f2tf32(g11));
    }
    __syncthreads();

    // ---------------- GEMM2: out = G @ W2 + b2 ----------------
    float c2[8][4];
    #pragma unroll
    for (int nt = 0; nt < 8; ++nt)
        #pragma unroll
        for (int j = 0; j < 4; ++j) c2[nt][j] = 0.f;

    #pragma unroll
    for (int k0 = 0; k0 < 8; ++k0) {
        int kk = k0 * 8;
        uint32_t a[4];
        const float* Ar = &A[(row0 + gid) * AP + kk + tid4];
        a[0] = __float_as_uint(Ar[0]);
        a[1] = __float_as_uint(Ar[8 * AP]);
        a[2] = __float_as_uint(Ar[4]);
        a[3] = __float_as_uint(Ar[8 * AP + 4]);
        #pragma unroll
        for (int nt = 0; nt < 8; ++nt) {
            uint32_t bf[2];
            const float* Bp = &W2[(kk + tid4) * WP + nt * 8 + gid];
            bf[0] = __float_as_uint(Bp[0]);
            bf[1] = __float_as_uint(Bp[4 * WP]);
            mma_tf32(c2[nt], a, bf);
        }
    }

    // stage result (with bias) in A, then coalesced store
    __syncthreads();   // all warps done reading A (gate)
    #pragma unroll
    for (int nt = 0; nt < 8; ++nt) {
        int col = nt * 8 + 2 * tid4;
        float bl0 = b2s[col], bl1 = b2s[col + 1];
        int r0 = row0 + gid, r1 = row0 + gid + 8;
        A[r0 * AP + col]     = c2[nt][0] + bl0;
        A[r0 * AP + col + 1] = c2[nt][1] + bl1;
        A[r1 * AP + col]     = c2[nt][2] + bl0;
        A[r1 * AP + col + 1] = c2[nt][3] + bl1;
    }
    __syncthreads();

    float4* op = (float4*)(out + tok0 * ODIM);
    for (int i = t; i < TILE_T * 16; i += 256) {
        int row = i >> 4;
        int k = (i & 15) << 2;
        op[i] = *(const float4*)&A[row * AP + k];
    }
}

// ---------------------------------------------------------------------------
extern "C" void kernel_launch(void* const* d_in, const int* in_sizes, int n_in,
                              void* d_out, int out_size) {
    (void)in_sizes; (void)n_in; (void)out_size;
    const float* q_data   = (const float*)d_in[0];
    const float* m_data   = (const float*)d_in[1];
    const float* q_mask   = (const float*)d_in[2];
    // d_in[3] = bias (dummy, unused by the reference math)
    const float* query_w  = (const float*)d_in[4];
    const float* key_w    = (const float*)d_in[5];
    const float* value_w  = (const float*)d_in[6];
    const float* gating_w = (const float*)d_in[7];
    const float* gating_b = (const float*)d_in[8];
    const float* output_w = (const float*)d_in[9];
    const float* output_b = (const float*)d_in[10];
    float* out = (float*)d_out;

    const int k3_smem = K3_SMEM_FLOATS * 4;   // 71680 B
    cudaFuncSetAttribute(k3_gate, cudaFuncAttributeMaxDynamicSharedMemorySize, k3_smem);

    k1_qavg<<<BB, 512>>>(q_data, q_mask);
    k2_attn<<<BB, 256>>>(m_data, q_mask, query_w, key_w, value_w);
    k3_gate<<<(BB * NN) / TILE_T, 256, k3_smem>>>(q_data, gating_w, gating_b,
                                                  output_w, output_b, out);
}